// round 17
// baseline (speedup 1.0000x reference)
#include <cuda_runtime.h>
#include <cuda_bf16.h>

// ChamferLoss via exact uniform-grid nearest neighbor (G=32), FULLY FUSED:
// one persistent kernel, software grid barriers between phases.
// pred[32768,3], target[32768,3] float32, out = mean NN^2 both directions.
//
// Phases: A hist -> B scan1 -> C scan2 -> D scatter -> E query -> F reduce.
// Grid barriers use monotonic epoch counters (never reset: replay-safe).

#define NPTS   32768
#define NALL   65536
#define G      32
#define NC     (G*G*G)       // 32768 cells per set
#define NC2    (2*NC)        // 65536
#define GLO    (-4.0f)
#define GH     (0.25f)       // 8/32, exact
#define GINV   (4.0f)        // 1/GH, exact
#define FINF   3.4e38f
#define NBLK   256

__device__ uint    g_cnt[NC2];       // zero at start of every run (phase B re-zeroes)
__device__ uint    g_scanpart[NC2];
__device__ uint    g_bsum[64];
__device__ uint    g_start[NC2 + 1];
__device__ uint    g_cursor[NC2];
__device__ float4  g_pts[NALL];      // cell-sorted; .w = original global idx bits
__device__ float   g_minv[NALL];     // per-ORIGINAL-index min sq distance
__device__ uint    g_bar[8];         // monotonic grid-barrier epoch counters

__device__ __forceinline__ void gridbar(int k) {
    __syncthreads();
    if (threadIdx.x == 0) {
        __threadfence();
        uint old = atomicAdd(&g_bar[k], 1u);
        uint target = ((old >> 8) + 1u) << 8;     // 256 arrivals per epoch
        while (atomicAdd(&g_bar[k], 0u) < target) __nanosleep(32);
        __threadfence();
    }
    __syncthreads();
}

__device__ __forceinline__ int cellof(float v) {
    int c = (int)floorf((v - GLO) * GINV);
    return min(max(c, 0), G - 1);
}
__device__ __forceinline__ float slabdist(float q, int c) {
    float l = GLO + c * GH;
    return fmaxf(0.0f, fmaxf(l - q, q - (l + GH)));
}
__device__ __forceinline__ void scan_range(uint k0, uint k1,
                                           float qx, float qy, float qz,
                                           float& best) {
    for (uint k = k0; k < k1; k++) {
        float4 p = g_pts[k];
        float dx = p.x - qx, dy = p.y - qy, dz = p.z - qz;
        best = fminf(best, fmaf(dx, dx, fmaf(dy, dy, dz * dz)));
    }
}

__global__ void __launch_bounds__(256)
k_fused(const float* __restrict__ pred, const float* __restrict__ target,
        float* __restrict__ out) {
    __shared__ uint  smu[256];
    __shared__ float smf[256];
    const int t   = threadIdx.x;
    const int gid = blockIdx.x * 256 + t;            // 0..NALL-1

    // ---------- load my point once; reused by phases A and D ----------
    const int s  = gid >> 15;
    const int li = gid & (NPTS - 1);
    const float* src = s ? target : pred;
    const float px = src[3 * li], py = src[3 * li + 1], pz = src[3 * li + 2];
    const int  pc = ((cellof(pz) * G + cellof(py)) * G + cellof(px)) + s * NC;

    // ---------- A: histogram (g_cnt zero on entry, every run) ----------
    atomicAdd(&g_cnt[pc], 1u);
    gridbar(0);

    // ---------- B: per-tile scan (blocks 0..63); re-zero g_cnt ----------
    if (blockIdx.x < 64) {
        int base = blockIdx.x * 1024 + t * 4;
        uint4 c4 = *(const uint4*)&g_cnt[base];
        *(uint4*)&g_cnt[base] = make_uint4(0, 0, 0, 0);   // clean for next replay
        uint sum = c4.x + c4.y + c4.z + c4.w;
        smu[t] = sum; __syncthreads();
        for (int off = 1; off < 256; off <<= 1) {
            uint v = (t >= off) ? smu[t - off] : 0u;
            __syncthreads();
            smu[t] += v;
            __syncthreads();
        }
        uint excl = smu[t] - sum;
        g_scanpart[base]     = excl;
        g_scanpart[base + 1] = excl + c4.x;
        g_scanpart[base + 2] = excl + c4.x + c4.y;
        g_scanpart[base + 3] = excl + c4.x + c4.y + c4.z;
        if (t == 255) g_bsum[blockIdx.x] = smu[255];
    }
    gridbar(1);

    // ---------- C: apply tile prefixes (blocks 0..63) ----------
    if (blockIdx.x < 64) {
        __shared__ uint soff;
        if (t < 32) {
            uint a = (2 * t     < (int)blockIdx.x) ? g_bsum[2 * t]     : 0u;
            uint b = (2 * t + 1 < (int)blockIdx.x) ? g_bsum[2 * t + 1] : 0u;
            uint v = a + b;
#pragma unroll
            for (int o = 16; o > 0; o >>= 1)
                v += __shfl_down_sync(0xFFFFFFFFu, v, o);
            if (t == 0) soff = v;
        }
        __syncthreads();
        uint off = soff;
        int base = blockIdx.x * 1024 + t * 4;
#pragma unroll
        for (int k = 0; k < 4; k++) {
            uint v = g_scanpart[base + k] + off;
            g_start[base + k] = v;
            g_cursor[base + k] = v;
        }
        if (blockIdx.x == 63 && t == 255) g_start[NC2] = NALL;
    }
    gridbar(2);

    // ---------- D: scatter (cell-sorted, carries original index) ----------
    {
        uint pos = atomicAdd(&g_cursor[pc], 1u);
        g_pts[pos] = make_float4(px, py, pz, __int_as_float(gid));
    }
    gridbar(3);

    // ---------- E: query (one thread per sorted position) ----------
    {
        int i = gid;                                 // sorted position
        float4 q = g_pts[i];
        int qs = i >> 15;
        int tb = (qs ^ 1) * NC;                      // target grid base
        float qx = q.x, qy = q.y, qz = q.z;
        int cx = cellof(qx), cy = cellof(qy), cz = cellof(qz);
        float ex = fmaxf(slabdist(qx, cx), fmaxf(slabdist(qy, cy), slabdist(qz, cz)));
        float best = FINF;

        // r = 1: prefetch all 9 rows' CSR boundaries, center row first, prune rest
        {
            int x0 = max(cx - 1, 0), x1 = min(cx + 1, G - 1);
            uint s0[9], s1[9];
#pragma unroll
            for (int dz = -1; dz <= 1; dz++) {
#pragma unroll
                for (int dy = -1; dy <= 1; dy++) {
                    int idx = (dz + 1) * 3 + (dy + 1);
                    int z = cz + dz, y = cy + dy;
                    bool ok = (z >= 0) && (z < G) && (y >= 0) && (y < G);
                    int zc = min(max(z, 0), G - 1), yc = min(max(y, 0), G - 1);
                    int rb = (zc * G + yc) * G + tb;
                    uint a = g_start[rb + x0];
                    uint b = g_start[rb + x1 + 1];
                    s0[idx] = ok ? a : 0u;
                    s1[idx] = ok ? b : 0u;
                }
            }
            scan_range(s0[4], s1[4], qx, qy, qz, best);
#pragma unroll
            for (int dz = -1; dz <= 1; dz++) {
                float dzs = slabdist(qz, cz + dz);
                float dz2 = dzs * dzs;
#pragma unroll
                for (int dy = -1; dy <= 1; dy++) {
                    if (dz == 0 && dy == 0) continue;
                    int idx = (dz + 1) * 3 + (dy + 1);
                    float dys = slabdist(qy, cy + dy);
                    if (fmaf(dys, dys, dz2) >= best) continue;
                    scan_range(s0[idx], s1[idx], qx, qy, qz, best);
                }
            }
        }

        // escalation: full pruned box per radius, exact termination
        int r = 1;
        for (;;) {
            float bnd = (float)r * GH - ex;
            if ((bnd > 0.0f && best <= bnd * bnd) || r >= G) break;
            r++;
            int z0 = max(cz - r, 0), z1 = min(cz + r, G - 1);
            int y0 = max(cy - r, 0), y1 = min(cy + r, G - 1);
            int x0 = max(cx - r, 0), x1 = min(cx + r, G - 1);
            for (int z = z0; z <= z1; z++) {
                float dzq = slabdist(qz, z);
                float dz2 = dzq * dzq;
                for (int y = y0; y <= y1; y++) {
                    float dyq = slabdist(qy, y);
                    if (fmaf(dyq, dyq, dz2) >= best) continue;
                    int rb = (z * G + y) * G + tb;
                    scan_range(g_start[rb + x0], g_start[rb + x1 + 1], qx, qy, qz, best);
                }
            }
        }
        g_minv[__float_as_int(q.w)] = best;   // by ORIGINAL index: deterministic
    }
    gridbar(4);

    // ---------- F: block 0 reduces (fixed order: deterministic) ----------
    if (blockIdx.x == 0) {
        float acc = 0.0f;
        const float4* mv = (const float4*)g_minv;
#pragma unroll
        for (int k = 0; k < NALL / 1024; k++) {      // 64 float4 per thread
            float4 v = mv[t + k * 256];
            acc += (v.x + v.y) + (v.z + v.w);
        }
        smf[t] = acc; __syncthreads();
        for (int stride = 128; stride > 0; stride >>= 1) {
            if (t < stride) smf[t] += smf[t + stride];
            __syncthreads();
        }
        if (t == 0) out[0] = smf[0] / (float)NPTS;
    }
}

extern "C" void kernel_launch(void* const* d_in, const int* in_sizes, int n_in,
                              void* d_out, int out_size) {
    const float* pred   = (const float*)d_in[0];
    const float* target = (const float*)d_in[1];
    float* out = (float*)d_out;
    k_fused<<<NBLK, 256>>>(pred, target, out);
}